// round 9
// baseline (speedup 1.0000x reference)
#include <cuda_runtime.h>
#include <cuda_fp16.h>

// ---------------------------------------------------------------------------
// Sinkhorn_seq: out = 0.001 * sum_b sinkhorn_loss(softmax(y_s/2), softmax(y_t/2))
// B=4, S=256, V=32000, TEMP=2, EPS=0.1, N_ITERS=10
//
//   k_softmax  : p = softmax(y/2) * 1024, stored as fp16      (2048 rows)
//   k_cdist    : Mpart = partial sum_v min(a,b) on half2      (V split 9 ways)
//                (rows sum to 1 => L1 = 2 - 2*sum min; min commutes with
//                 monotone fp16 rounding)
//   k_reduceWK : M = sum_s Mpart; W = 2 - 2M/1024; K = exp(-W/0.1)
//   k_sinkhorn : u/v diagonal scaling (== alternating row/col normalization)
//   k_final    : out = 0.001 * sum_b loss_b
// ---------------------------------------------------------------------------

#define BATCH 4
#define SEQ   256
#define VOC   32000
#define NS    9           // V splits -> grid 9*4*4 = 144 CTAs = ONE wave
#define VLEN  3584        // per-split V (multiple of 64; split 8 gets 3328)
#define SROW  132         // smem row stride in half2 units (128 + 4 pad)
#define HBUF  (32 * SROW) // one tile buffer (uints)
#define CD_SMEM (4 * HBUF * 4)  // bytes: 2 buffers x (As+Bs)

__device__ __half g_ps[BATCH * SEQ * VOC];
__device__ __half g_pt[BATCH * SEQ * VOC];
__device__ float  g_Mpart[NS * BATCH * SEQ * SEQ];
__device__ float  g_W[BATCH * SEQ * SEQ];
__device__ float  g_K[BATCH * SEQ * SEQ];
__device__ float  g_loss[BATCH];

__device__ __forceinline__ float ex2(float x) {
    float r;
    asm("ex2.approx.ftz.f32 %0, %1;" : "=f"(r) : "f"(x));
    return r;
}
__device__ __forceinline__ __half2 u2h2(unsigned int u) {
    __half2 h;
    *reinterpret_cast<unsigned int*>(&h) = u;
    return h;
}
__device__ __forceinline__ void stg_cs_f4(float* p, float4 v) {
    asm volatile("st.global.cs.v4.f32 [%0], {%1, %2, %3, %4};"
                 :: "l"(p), "f"(v.x), "f"(v.y), "f"(v.z), "f"(v.w) : "memory");
}
__device__ __forceinline__ float ldg_cs_f(const float* p) {
    float r;
    asm volatile("ld.global.cs.f32 %0, [%1];" : "=f"(r) : "l"(p));
    return r;
}

// ---------------------------------------------------------------------------
// Softmax: one block per row (8000 float4 in registers, 8/thread).
// ex2 computed ONCE per element. Output fp16, scaled by 1024.
// ---------------------------------------------------------------------------
__global__ __launch_bounds__(1024) void k_softmax(const float* __restrict__ ys,
                                                  const float* __restrict__ yt) {
    int bid = blockIdx.x;                 // 0..2047
    int tensor = bid >> 10;
    int row = bid & 1023;
    const float* x = (tensor ? yt : ys) + (size_t)row * VOC;
    __half*      p = (tensor ? g_pt : g_ps) + (size_t)row * VOC;

    int tid = threadIdx.x;
    float4 vals[8];
    float m = -3.0e38f;
#pragma unroll
    for (int k = 0; k < 8; k++) {
        int idx = tid + k * 1024;
        if (idx < 8000) vals[k] = ((const float4*)x)[idx];
        else            vals[k] = make_float4(-1e30f, -1e30f, -1e30f, -1e30f);
        m = fmaxf(m, fmaxf(fmaxf(vals[k].x, vals[k].y), fmaxf(vals[k].z, vals[k].w)));
    }

    __shared__ float red[1024];
    red[tid] = m;
    __syncthreads();
    for (int off = 512; off; off >>= 1) {
        if (tid < off) red[tid] = fmaxf(red[tid], red[tid + off]);
        __syncthreads();
    }
    m = red[0];
    __syncthreads();

    const float C = 0.7213475204444817f;  // 0.5 * log2(e)   (temperature 2)
    float s = 0.0f;
#pragma unroll
    for (int k = 0; k < 8; k++) {
        vals[k].x = ex2((vals[k].x - m) * C);
        vals[k].y = ex2((vals[k].y - m) * C);
        vals[k].z = ex2((vals[k].z - m) * C);
        vals[k].w = ex2((vals[k].w - m) * C);
        s += vals[k].x + vals[k].y + vals[k].z + vals[k].w;
    }
    red[tid] = s;
    __syncthreads();
    for (int off = 512; off; off >>= 1) {
        if (tid < off) red[tid] += red[tid + off];
        __syncthreads();
    }
    float r1024 = 1024.0f / red[0];       // scale folded into normalization

#pragma unroll
    for (int k = 0; k < 8; k++) {
        int idx = tid + k * 1024;
        if (idx < 8000) {
            __half2 h0 = __floats2half2_rn(vals[k].x * r1024, vals[k].y * r1024);
            __half2 h1 = __floats2half2_rn(vals[k].z * r1024, vals[k].w * r1024);
            uint2 st;
            st.x = *reinterpret_cast<unsigned int*>(&h0);
            st.y = *reinterpret_cast<unsigned int*>(&h1);
            ((uint2*)p)[idx] = st;
        }
    }
}

// ---------------------------------------------------------------------------
// cdist min-sum, half2 datapath, double-buffered smem (1 sync per chunk).
// grid (NS, 4 tiles, BATCH) = 144 CTAs (one wave), 512 threads;
// 128x128 tile, 8x4 half2 accums/thread, flushed to fp32 every 64 v
// (flush interval is error-budget-critical: do not extend).
// Chunk = 64 v (32 half2 rows), v-major, XOR-bit4 swizzle keyed on (vp & 16):
// conflict-free transpose stores AND conflict-free LDS.128 compute loads.
// iter k: store chunk k+1 (prefetched), issue LDG chunk k+2, compute chunk k.
// ---------------------------------------------------------------------------
__global__ __launch_bounds__(512) void k_cdist() {
    extern __shared__ __align__(16) unsigned int dyn[];

    int s  = blockIdx.x;
    int ti = blockIdx.y >> 1, tj = blockIdx.y & 1;
    int b  = blockIdx.z;

    const __half* A  = g_ps + (size_t)(b * SEQ + ti * 128) * VOC;
    const __half* Bp = g_pt + (size_t)(b * SEQ + tj * 128) * VOC;

    int tid = threadIdx.x;
    int tx = tid & 31, ty = tid >> 5;        // j = tx*4+c, i = ty*8+r

    // hoisted swizzled compute offsets (half=0: ^0, half=1: ^16)
    int oa0 = ty * 8,        oa1 = (ty * 8) ^ 16;
    int ob0 = tx * 4,        ob1 = (tx * 4) ^ 16;

    // loader: threads 0..255 -> A, 256..511 -> B; 2 threads per row (64B each)
    int lt = tid & 255;
    int lvg = lt & 1, lrow = lt >> 1;
    int lcol = lrow ^ (lvg << 4);            // hoisted swizzled column
    const char* gbase = (const char*)(((tid < 256) ? A : Bp) + (size_t)lrow * VOC + lvg * 32);
    unsigned int* sdst = dyn + ((tid < 256) ? 0 : HBUF) + lcol + (lvg * 16) * SROW;

    float acc[8][4];
#pragma unroll
    for (int r = 0; r < 8; r++)
#pragma unroll
        for (int c = 0; c < 4; c++) acc[r][c] = 0.0f;

    int v0 = s * VLEN;
    int nch = (min(VOC, v0 + VLEN) - v0) >> 6;   // 56 (52 for last split)

    uint4 pf[4];
#define LOAD_PF(chunk) do {                                                   \
        const uint4* gp = (const uint4*)(gbase + ((size_t)(v0 + (chunk) * 64) << 1)); \
        pf[0] = gp[0]; pf[1] = gp[1]; pf[2] = gp[2]; pf[3] = gp[3];           \
    } while (0)
#define STORE_PF(buf) do {                                                    \
        unsigned int* dst = sdst + (buf) * (2 * HBUF);                        \
        _Pragma("unroll")                                                     \
        for (int k = 0; k < 4; k++) {                                         \
            dst[(k * 4 + 0) * SROW] = pf[k].x;                                \
            dst[(k * 4 + 1) * SROW] = pf[k].y;                                \
            dst[(k * 4 + 2) * SROW] = pf[k].z;                                \
            dst[(k * 4 + 3) * SROW] = pf[k].w;                                \
        }                                                                     \
    } while (0)

    // prologue: chunk 0 into buffer 0, prefetch chunk 1
    LOAD_PF(0);
    STORE_PF(0);
    if (nch > 1) LOAD_PF(1);
    __syncthreads();

    for (int k = 0; k < nch; k++) {
        // store chunk k+1 into the other buffer (chunk k-1 fully consumed
        // before the sync that ended iteration k-1); pf holds k+1, so the
        // k+2 LDGs are issued right after the store consumes pf.
        if (k + 1 < nch) STORE_PF((k + 1) & 1);
        if (k + 2 < nch) LOAD_PF(k + 2);

        const unsigned int* AsC = dyn + (k & 1) * (2 * HBUF);
        const unsigned int* BsC = AsC + HBUF;

        // ---- compute: HMNMX2 + HADD2, 1 instruction per 2 elements ----
        __half2 hAcc[8][4];
        __half2 hz = __float2half2_rn(0.0f);
#pragma unroll
        for (int r = 0; r < 8; r++)
#pragma unroll
            for (int c = 0; c < 4; c++) hAcc[r][c] = hz;

#pragma unroll
        for (int half = 0; half < 2; half++) {
            const unsigned int* aBase = AsC + (half * 16) * SROW + (half ? oa1 : oa0);
            const unsigned int* bBase = BsC + (half * 16) * SROW + (half ? ob1 : ob0);
#pragma unroll
            for (int vp = 0; vp < 16; vp++) {
                const uint4* pa = (const uint4*)(aBase + vp * SROW);
                uint4 a0 = pa[0], a1 = pa[1];
                uint4 bq = *(const uint4*)(bBase + vp * SROW);
                __half2 a2[8] = {u2h2(a0.x), u2h2(a0.y), u2h2(a0.z), u2h2(a0.w),
                                 u2h2(a1.x), u2h2(a1.y), u2h2(a1.z), u2h2(a1.w)};
                __half2 b2[4] = {u2h2(bq.x), u2h2(bq.y), u2h2(bq.z), u2h2(bq.w)};
#pragma unroll
                for (int c = 0; c < 4; c++) {
                    __half2 bc = b2[c];
#pragma unroll
                    for (int r = 0; r < 8; r++)
                        hAcc[r][c] = __hadd2(hAcc[r][c], __hmin2(a2[r], bc));
                }
            }
        }

        // ---- flush chunk sums to fp32 (bounds fp16 accumulation error) ----
#pragma unroll
        for (int r = 0; r < 8; r++)
#pragma unroll
            for (int c = 0; c < 4; c++) {
                float2 f = __half22float2(hAcc[r][c]);
                acc[r][c] += f.x + f.y;
            }
        __syncthreads();
    }

    // ---- write partial tile (streaming: written once, read once) ----
    float* out = g_Mpart + (size_t)(s * BATCH + b) * (SEQ * SEQ);
#pragma unroll
    for (int r = 0; r < 8; r++) {
        float4 o = make_float4(acc[r][0], acc[r][1], acc[r][2], acc[r][3]);
        stg_cs_f4(out + (ti * 128 + ty * 8 + r) * SEQ + tj * 128 + tx * 4, o);
    }
}

// ---------------------------------------------------------------------------
// M = sum_s Mpart (scaled by 1024);  W = 2 - 2M/1024;  K = exp(-W/0.1)
// Mpart read streaming (touched once) to keep g_K L2-resident for k_sinkhorn.
// ---------------------------------------------------------------------------
__global__ __launch_bounds__(256) void k_reduceWK() {
    int idx = blockIdx.x * 256 + threadIdx.x;  // 0 .. 262143
    float m = 0.0f;
#pragma unroll
    for (int s = 0; s < NS; s++)
        m += ldg_cs_f(&g_Mpart[(size_t)s * (BATCH * SEQ * SEQ) + idx]);
    float Wv = 2.0f - 0.001953125f * m;        // 2 - 2*(m/1024)
    g_W[idx] = Wv;
    g_K[idx] = ex2(-14.426950408889634f * Wv); // exp(-10*W)
}

// ---------------------------------------------------------------------------
// Sinkhorn diagonal scaling: u = 1/(K v); v = 1/(K^T u); loss = sum u K v W
// ---------------------------------------------------------------------------
__global__ __launch_bounds__(1024) void k_sinkhorn() {
    int b = blockIdx.x;
    const float* __restrict__ K = g_K + (size_t)b * (SEQ * SEQ);
    const float* __restrict__ W = g_W + (size_t)b * (SEQ * SEQ);

    __shared__ float su[SEQ], sv[SEQ], red[1024];
    int tid = threadIdx.x, lane = tid & 31, w = tid >> 5;

    if (tid < SEQ) sv[tid] = 1.0f;
    __syncthreads();

    for (int it = 0; it < 10; it++) {
#pragma unroll
        for (int rr = 0; rr < 8; rr++) {
            int i = w * 8 + rr;
            float sum = 0.0f;
#pragma unroll
            for (int k = 0; k < 8; k++) {
                int j = lane + 32 * k;
                sum += K[i * SEQ + j] * sv[j];
            }
#pragma unroll
            for (int off = 16; off; off >>= 1) sum += __shfl_down_sync(0xffffffffu, sum, off);
            if (lane == 0) su[i] = 1.0f / sum;
        }
        __syncthreads();

        {
            int j = tid & 255, q = tid >> 8;
            float sum = 0.0f;
#pragma unroll
            for (int k = 0; k < 64; k++) {
                int i = q * 64 + k;
                sum += K[i * SEQ + j] * su[i];
            }
            red[tid] = sum;
            __syncthreads();
            if (tid < SEQ)
                sv[tid] = 1.0f / (red[tid] + red[tid + 256] + red[tid + 512] + red[tid + 768]);
            __syncthreads();
        }
    }

    float part = 0.0f;
    for (int e = tid; e < SEQ * SEQ; e += 1024)
        part += su[e >> 8] * sv[e & 255] * K[e] * W[e];
    red[tid] = part;
    __syncthreads();
    for (int off = 512; off; off >>= 1) {
        if (tid < off) red[tid] += red[tid + off];
        __syncthreads();
    }
    if (tid == 0) g_loss[b] = red[0];
}

__global__ __launch_bounds__(32) void k_final(float* out) {
    if (threadIdx.x == 0)
        out[0] = 0.001f * (g_loss[0] + g_loss[1] + g_loss[2] + g_loss[3]);
}

// ---------------------------------------------------------------------------
extern "C" void kernel_launch(void* const* d_in, const int* in_sizes, int n_in,
                              void* d_out, int out_size) {
    const float* ys = (const float*)d_in[0];
    const float* yt = (const float*)d_in[1];
    float* out = (float*)d_out;

    // 66KB dynamic smem for the double-buffered cdist (host-side attribute,
    // idempotent, not a stream op -> graph-capture safe)
    cudaFuncSetAttribute(k_cdist, cudaFuncAttributeMaxDynamicSharedMemorySize, CD_SMEM);

    k_softmax<<<2048, 1024>>>(ys, yt);
    k_cdist<<<dim3(NS, 4, BATCH), 512, CD_SMEM>>>();
    k_reduceWK<<<(BATCH * SEQ * SEQ) / 256, 256>>>();
    k_sinkhorn<<<BATCH, 1024>>>();
    k_final<<<1, 32>>>(out);
}

// round 16
// speedup vs baseline: 1.0610x; 1.0610x over previous
#include <cuda_runtime.h>
#include <cuda_fp16.h>

// ---------------------------------------------------------------------------
// Sinkhorn_seq: out = 0.001 * sum_b sinkhorn_loss(softmax(y_s/2), softmax(y_t/2))
// B=4, S=256, V=32000, TEMP=2, EPS=0.1, N_ITERS=10
//
//   k_softmax  : p = softmax(y/2) * 1024, stored as fp16      (2048 rows)
//   k_cdist    : Mpart = partial sum_v min(a,b) on half2      (V split 9 ways)
//   k_reduceWK : W = 2 - 2M/1024 ; per-batch minW via atomicMin
//   k_sinkhorn : K~ = 256*exp(-10(W-minW)) in SMEM fp16 (scale-invariant),
//                u/v diagonal scaling fully smem-resident, loss = sum uK~vW
//   k_final    : out = 0.001 * sum_b loss_b
// ---------------------------------------------------------------------------

#define BATCH 4
#define SEQ   256
#define VOC   32000
#define NS    9           // V splits -> grid 9*4*4 = 144 CTAs = ONE wave
#define VLEN  3584        // per-split V (multiple of 64; split 8 gets 3328)
#define SROW  132         // smem row stride in half2 units (128 + 4 pad)
#define HBUF  (32 * SROW) // one tile buffer (uints)
#define CD_SMEM (4 * HBUF * 4)  // bytes: 2 buffers x (As+Bs)
// sinkhorn smem: K~ 32768 half2 + su 256 f + sv2 128 f2 + red2 1024 f2
#define SK_SMEM (32768 * 4 + 256 * 4 + 128 * 8 + 1024 * 8)

__device__ __half g_ps[BATCH * SEQ * VOC];
__device__ __half g_pt[BATCH * SEQ * VOC];
__device__ float  g_Mpart[NS * BATCH * SEQ * SEQ];
__device__ float  g_W[BATCH * SEQ * SEQ];
__device__ int    g_minWbits[BATCH];
__device__ float  g_loss[BATCH];

__device__ __forceinline__ float ex2(float x) {
    float r;
    asm("ex2.approx.ftz.f32 %0, %1;" : "=f"(r) : "f"(x));
    return r;
}
__device__ __forceinline__ __half2 u2h2(unsigned int u) {
    __half2 h;
    *reinterpret_cast<unsigned int*>(&h) = u;
    return h;
}
__device__ __forceinline__ void stg_cs_f4(float* p, float4 v) {
    asm volatile("st.global.cs.v4.f32 [%0], {%1, %2, %3, %4};"
                 :: "l"(p), "f"(v.x), "f"(v.y), "f"(v.z), "f"(v.w) : "memory");
}
__device__ __forceinline__ float ldg_cs_f(const float* p) {
    float r;
    asm volatile("ld.global.cs.f32 %0, [%1];" : "=f"(r) : "l"(p));
    return r;
}

// ---------------------------------------------------------------------------
// Softmax: one block per row (8000 float4 in registers, 8/thread).
// Also resets g_minWbits each run (kernel-boundary ordered before reduceWK).
// ---------------------------------------------------------------------------
__global__ __launch_bounds__(1024) void k_softmax(const float* __restrict__ ys,
                                                  const float* __restrict__ yt) {
    if (blockIdx.x == 0 && threadIdx.x < BATCH)
        g_minWbits[threadIdx.x] = 0x7F800000;   // +inf

    int bid = blockIdx.x;                 // 0..2047
    int tensor = bid >> 10;
    int row = bid & 1023;
    const float* x = (tensor ? yt : ys) + (size_t)row * VOC;
    __half*      p = (tensor ? g_pt : g_ps) + (size_t)row * VOC;

    int tid = threadIdx.x;
    float4 vals[8];
    float m = -3.0e38f;
#pragma unroll
    for (int k = 0; k < 8; k++) {
        int idx = tid + k * 1024;
        if (idx < 8000) vals[k] = ((const float4*)x)[idx];
        else            vals[k] = make_float4(-1e30f, -1e30f, -1e30f, -1e30f);
        m = fmaxf(m, fmaxf(fmaxf(vals[k].x, vals[k].y), fmaxf(vals[k].z, vals[k].w)));
    }

    __shared__ float red[1024];
    red[tid] = m;
    __syncthreads();
    for (int off = 512; off; off >>= 1) {
        if (tid < off) red[tid] = fmaxf(red[tid], red[tid + off]);
        __syncthreads();
    }
    m = red[0];
    __syncthreads();

    const float C = 0.7213475204444817f;  // 0.5 * log2(e)   (temperature 2)
    float s = 0.0f;
#pragma unroll
    for (int k = 0; k < 8; k++) {
        vals[k].x = ex2((vals[k].x - m) * C);
        vals[k].y = ex2((vals[k].y - m) * C);
        vals[k].z = ex2((vals[k].z - m) * C);
        vals[k].w = ex2((vals[k].w - m) * C);
        s += vals[k].x + vals[k].y + vals[k].z + vals[k].w;
    }
    red[tid] = s;
    __syncthreads();
    for (int off = 512; off; off >>= 1) {
        if (tid < off) red[tid] += red[tid + off];
        __syncthreads();
    }
    float r1024 = 1024.0f / red[0];       // scale folded into normalization

#pragma unroll
    for (int k = 0; k < 8; k++) {
        int idx = tid + k * 1024;
        if (idx < 8000) {
            __half2 h0 = __floats2half2_rn(vals[k].x * r1024, vals[k].y * r1024);
            __half2 h1 = __floats2half2_rn(vals[k].z * r1024, vals[k].w * r1024);
            uint2 st;
            st.x = *reinterpret_cast<unsigned int*>(&h0);
            st.y = *reinterpret_cast<unsigned int*>(&h1);
            ((uint2*)p)[idx] = st;
        }
    }
}

// ---------------------------------------------------------------------------
// cdist min-sum, half2 datapath, double-buffered smem (1 sync per chunk).
// grid (NS, 4 tiles, BATCH) = 144 CTAs (one wave), 512 threads;
// 128x128 tile, 8x4 half2 accums/thread, flushed to fp32 every 64 v.
// ---------------------------------------------------------------------------
__global__ __launch_bounds__(512) void k_cdist() {
    extern __shared__ __align__(16) unsigned int dyn[];

    int s  = blockIdx.x;
    int ti = blockIdx.y >> 1, tj = blockIdx.y & 1;
    int b  = blockIdx.z;

    const __half* A  = g_ps + (size_t)(b * SEQ + ti * 128) * VOC;
    const __half* Bp = g_pt + (size_t)(b * SEQ + tj * 128) * VOC;

    int tid = threadIdx.x;
    int tx = tid & 31, ty = tid >> 5;        // j = tx*4+c, i = ty*8+r

    int oa0 = ty * 8,        oa1 = (ty * 8) ^ 16;
    int ob0 = tx * 4,        ob1 = (tx * 4) ^ 16;

    int lt = tid & 255;
    int lvg = lt & 1, lrow = lt >> 1;
    int lcol = lrow ^ (lvg << 4);
    const char* gbase = (const char*)(((tid < 256) ? A : Bp) + (size_t)lrow * VOC + lvg * 32);
    unsigned int* sdst = dyn + ((tid < 256) ? 0 : HBUF) + lcol + (lvg * 16) * SROW;

    float acc[8][4];
#pragma unroll
    for (int r = 0; r < 8; r++)
#pragma unroll
        for (int c = 0; c < 4; c++) acc[r][c] = 0.0f;

    int v0 = s * VLEN;
    int nch = (min(VOC, v0 + VLEN) - v0) >> 6;

    uint4 pf[4];
#define LOAD_PF(chunk) do {                                                   \
        const uint4* gp = (const uint4*)(gbase + ((size_t)(v0 + (chunk) * 64) << 1)); \
        pf[0] = gp[0]; pf[1] = gp[1]; pf[2] = gp[2]; pf[3] = gp[3];           \
    } while (0)
#define STORE_PF(buf) do {                                                    \
        unsigned int* dst = sdst + (buf) * (2 * HBUF);                        \
        _Pragma("unroll")                                                     \
        for (int k = 0; k < 4; k++) {                                         \
            dst[(k * 4 + 0) * SROW] = pf[k].x;                                \
            dst[(k * 4 + 1) * SROW] = pf[k].y;                                \
            dst[(k * 4 + 2) * SROW] = pf[k].z;                                \
            dst[(k * 4 + 3) * SROW] = pf[k].w;                                \
        }                                                                     \
    } while (0)

    LOAD_PF(0);
    STORE_PF(0);
    if (nch > 1) LOAD_PF(1);
    __syncthreads();

    for (int k = 0; k < nch; k++) {
        if (k + 1 < nch) STORE_PF((k + 1) & 1);
        if (k + 2 < nch) LOAD_PF(k + 2);

        const unsigned int* AsC = dyn + (k & 1) * (2 * HBUF);
        const unsigned int* BsC = AsC + HBUF;

        __half2 hAcc[8][4];
        __half2 hz = __float2half2_rn(0.0f);
#pragma unroll
        for (int r = 0; r < 8; r++)
#pragma unroll
            for (int c = 0; c < 4; c++) hAcc[r][c] = hz;

#pragma unroll
        for (int half = 0; half < 2; half++) {
            const unsigned int* aBase = AsC + (half * 16) * SROW + (half ? oa1 : oa0);
            const unsigned int* bBase = BsC + (half * 16) * SROW + (half ? ob1 : ob0);
#pragma unroll
            for (int vp = 0; vp < 16; vp++) {
                const uint4* pa = (const uint4*)(aBase + vp * SROW);
                uint4 a0 = pa[0], a1 = pa[1];
                uint4 bq = *(const uint4*)(bBase + vp * SROW);
                __half2 a2[8] = {u2h2(a0.x), u2h2(a0.y), u2h2(a0.z), u2h2(a0.w),
                                 u2h2(a1.x), u2h2(a1.y), u2h2(a1.z), u2h2(a1.w)};
                __half2 b2[4] = {u2h2(bq.x), u2h2(bq.y), u2h2(bq.z), u2h2(bq.w)};
#pragma unroll
                for (int c = 0; c < 4; c++) {
                    __half2 bc = b2[c];
#pragma unroll
                    for (int r = 0; r < 8; r++)
                        hAcc[r][c] = __hadd2(hAcc[r][c], __hmin2(a2[r], bc));
                }
            }
        }

#pragma unroll
        for (int r = 0; r < 8; r++)
#pragma unroll
            for (int c = 0; c < 4; c++) {
                float2 f = __half22float2(hAcc[r][c]);
                acc[r][c] += f.x + f.y;
            }
        __syncthreads();
    }

    float* out = g_Mpart + (size_t)(s * BATCH + b) * (SEQ * SEQ);
#pragma unroll
    for (int r = 0; r < 8; r++) {
        float4 o = make_float4(acc[r][0], acc[r][1], acc[r][2], acc[r][3]);
        stg_cs_f4(out + (ti * 128 + ty * 8 + r) * SEQ + tj * 128 + tx * 4, o);
    }
}

// ---------------------------------------------------------------------------
// W = 2 - 2M/1024 ; per-batch min(W) via block-reduce + atomicMin (positive
// floats compare correctly as ints; min is order-independent -> deterministic)
// ---------------------------------------------------------------------------
__global__ __launch_bounds__(256) void k_reduceWK() {
    int idx = blockIdx.x * 256 + threadIdx.x;  // 0 .. 262143
    float m = 0.0f;
#pragma unroll
    for (int s = 0; s < NS; s++)
        m += ldg_cs_f(&g_Mpart[(size_t)s * (BATCH * SEQ * SEQ) + idx]);
    float Wv = 2.0f - 0.001953125f * m;        // 2 - 2*(m/1024)
    g_W[idx] = Wv;

    __shared__ float rmin[256];
    rmin[threadIdx.x] = Wv;
    __syncthreads();
    for (int off = 128; off; off >>= 1) {
        if (threadIdx.x < off)
            rmin[threadIdx.x] = fminf(rmin[threadIdx.x], rmin[threadIdx.x + off]);
        __syncthreads();
    }
    if (threadIdx.x == 0)
        atomicMin(&g_minWbits[blockIdx.x >> 8], __float_as_int(rmin[0]));
}

// ---------------------------------------------------------------------------
// Sinkhorn, fully SMEM-resident. Scale invariance: K -> cK leaves P and the
// loss unchanged, so use K~ = 2^8 * exp(-10*(W - minW)) stored as fp16 in
// smem (all entries fp16-normal). 10 iters of u = 1/(K~ v), v = 1/(K~^T u),
// then loss = sum u K~ v W (scale cancels exactly).
// ---------------------------------------------------------------------------
__global__ __launch_bounds__(1024) void k_sinkhorn() {
    extern __shared__ __align__(16) unsigned int sk[];  // K~ as half2 [256][128]
    float*  su   = (float*)(sk + 32768);                // [256]
    float2* sv2  = (float2*)(su + 256);                 // [128]
    float2* red2 = (float2*)(sv2 + 128);                // [1024]

    int b = blockIdx.x;
    const float* __restrict__ Wb = g_W + (size_t)b * (SEQ * SEQ);
    int tid = threadIdx.x, lane = tid & 31, w = tid >> 5;

    float minW = __int_as_float(g_minWbits[b]);

    // ---- load W, build scaled fp16 kernel in smem ----
    const float LOG2E10 = 14.426950408889634f;          // 10 * log2(e)
    for (int e = tid; e < 32768; e += 1024) {
        float2 w2 = ((const float2*)Wb)[e];
        float k0 = ex2(fmaf(-LOG2E10, w2.x - minW, 8.0f));
        float k1 = ex2(fmaf(-LOG2E10, w2.y - minW, 8.0f));
        __half2 h = __floats2half2_rn(k0, k1);
        sk[e] = *reinterpret_cast<unsigned int*>(&h);
    }
    if (tid < 128) sv2[tid] = make_float2(1.0f, 1.0f);
    __syncthreads();

    for (int it = 0; it < 10; it++) {
        // rows: warp w handles i = w*8..w*8+7 ; su[i] = 1/(K~ v)_i
#pragma unroll
        for (int rr = 0; rr < 8; rr++) {
            int i = w * 8 + rr;
            const unsigned int* row = sk + i * 128;
            float sum = 0.0f;
#pragma unroll
            for (int k = 0; k < 4; k++) {
                int j2 = lane + 32 * k;
                float2 f = __half22float2(u2h2(row[j2]));
                float2 s = sv2[j2];
                sum = fmaf(f.x, s.x, fmaf(f.y, s.y, sum));
            }
#pragma unroll
            for (int off = 16; off; off >>= 1) sum += __shfl_down_sync(0xffffffffu, sum, off);
            if (lane == 0) su[i] = 1.0f / sum;
        }
        __syncthreads();

        // cols: sv2[j2] = 1/(K~^T u) for columns 2*j2, 2*j2+1
        {
            int j2 = tid & 127, q = tid >> 7;           // 8 i-groups of 32
            float2 sum = make_float2(0.0f, 0.0f);
#pragma unroll
            for (int k = 0; k < 32; k++) {
                int i = q * 32 + k;
                float2 f = __half22float2(u2h2(sk[i * 128 + j2]));
                float ui = su[i];
                sum.x = fmaf(f.x, ui, sum.x);
                sum.y = fmaf(f.y, ui, sum.y);
            }
            red2[tid] = sum;
            __syncthreads();
            if (tid < 128) {
                float2 t = make_float2(0.0f, 0.0f);
#pragma unroll
                for (int g = 0; g < 8; g++) {
                    float2 r = red2[tid + 128 * g];
                    t.x += r.x; t.y += r.y;
                }
                sv2[tid] = make_float2(1.0f / t.x, 1.0f / t.y);
            }
            __syncthreads();
        }
    }

    // ---- loss_b = sum_ij u_i K~_ij v_j W_ij  (scale cancels) ----
    float part = 0.0f;
    for (int e = tid; e < 32768; e += 1024) {
        float2 w2 = ((const float2*)Wb)[e];
        float2 f = __half22float2(u2h2(sk[e]));
        float2 s = sv2[e & 127];
        part += su[e >> 7] * (f.x * s.x * w2.x + f.y * s.y * w2.y);
    }
    float* red = (float*)red2;
    red[tid] = part;
    __syncthreads();
    for (int off = 512; off; off >>= 1) {
        if (tid < off) red[tid] += red[tid + off];
        __syncthreads();
    }
    if (tid == 0) g_loss[b] = red[0];
}

__global__ __launch_bounds__(32) void k_final(float* out) {
    if (threadIdx.x == 0)
        out[0] = 0.001f * (g_loss[0] + g_loss[1] + g_loss[2] + g_loss[3]);
}

// ---------------------------------------------------------------------------
extern "C" void kernel_launch(void* const* d_in, const int* in_sizes, int n_in,
                              void* d_out, int out_size) {
    const float* ys = (const float*)d_in[0];
    const float* yt = (const float*)d_in[1];
    float* out = (float*)d_out;

    cudaFuncSetAttribute(k_cdist, cudaFuncAttributeMaxDynamicSharedMemorySize, CD_SMEM);
    cudaFuncSetAttribute(k_sinkhorn, cudaFuncAttributeMaxDynamicSharedMemorySize, SK_SMEM);

    k_softmax<<<2048, 1024>>>(ys, yt);
    k_cdist<<<dim3(NS, 4, BATCH), 512, CD_SMEM>>>();
    k_reduceWK<<<(BATCH * SEQ * SEQ) / 256, 256>>>();
    k_sinkhorn<<<BATCH, 1024, SK_SMEM>>>();
    k_final<<<1, 32>>>(out);
}